// round 2
// baseline (speedup 1.0000x reference)
#include <cuda_runtime.h>
#include <cstdint>

#define LDK 132                      // padded row length in floats (132 % 32 == 4 -> conflict-free)
#define TILE_B (128 * LDK * 4)       // 67584 bytes per 128x128 fp32 tile

#define SM_X   0
#define SM_Y0  TILE_B
#define SM_Y1  (2 * TILE_B)
#define SM_X2  (3 * TILE_B)          // 128 floats
#define SM_Y2  (3 * TILE_B + 512)    // 128 floats
#define SMEM_TOTAL (3 * TILE_B + 1024)

__device__ __forceinline__ uint32_t smem_u32(const void* p) {
    uint32_t a;
    asm("{ .reg .u64 t; cvta.to.shared.u64 t, %1; cvt.u32.u64 %0, t; }" : "=r"(a) : "l"(p));
    return a;
}

__device__ __forceinline__ void cp_async16(uint32_t dst, const float* src) {
    asm volatile("cp.async.cg.shared.global [%0], [%1], 16;" :: "r"(dst), "l"(src));
}
__device__ __forceinline__ void cp_commit() {
    asm volatile("cp.async.commit_group;" ::: "memory");
}
template <int N>
__device__ __forceinline__ void cp_wait() {
    asm volatile("cp.async.wait_group %0;" :: "n"(N) : "memory");
}

// issue one 128x128 fp32 tile load: global row-major (ld 128) -> smem padded (ld 132)
__device__ __forceinline__ void load_tile_async(uint32_t sdst, const float* __restrict__ g, int tid) {
#pragma unroll
    for (int i = 0; i < 16; ++i) {
        int idx = i * 256 + tid;
        int r = idx >> 5, c4 = idx & 31;
        cp_async16(sdst + (uint32_t)(r * LDK + c4 * 4) * 4u, g + r * 128 + c4 * 4);
    }
}

__device__ __forceinline__ float rowsum128(const float* __restrict__ p) {
    float s = 0.f;
#pragma unroll
    for (int i = 0; i < 32; ++i) {
        float4 v = *(const float4*)(p + 4 * i);
        s += v.x * v.x + v.y * v.y + v.z * v.z + v.w * v.w;
    }
    return s;
}

__global__ void __launch_bounds__(256, 1)
pairwise_cost_kernel(const float* __restrict__ x, const float* __restrict__ y,
                     float* __restrict__ out) {
    extern __shared__ char smem[];
    float* sf = (float*)smem;
    const uint32_t sb = smem_u32(smem);
    const int tid = threadIdx.x, lane = tid & 31, wid = tid >> 5;

    const int bxn = blockIdx.x;   // n-chunk (512 wide)
    const int bym = blockIdx.y;   // m tile (128 rows)
    const int bz  = blockIdx.z;   // batch

    const float* xg = x + ((size_t)(bz * 2048 + bym * 128)) * 128;
    const float* yg = y + ((size_t)(bz * 2048 + bxn * 512)) * 128;

    // ---- prologue: x tile + first two y tiles in flight ----
    load_tile_async(sb + SM_X, xg, tid);               cp_commit();
    load_tile_async(sb + SM_Y0, yg, tid);              cp_commit();
    load_tile_async(sb + SM_Y1, yg + 128 * 128, tid);  cp_commit();
    cp_wait<2>();                                      // x ready
    __syncthreads();

    if (tid < 128) sf[SM_X2 / 4 + tid] = rowsum128(sf + tid * LDK);
    __syncthreads();

    // per-thread x2 registers (8 output rows per thread)
    const int m0  = (wid >> 2) * 64;
    const int n0w = (wid & 3) * 32;
    float x2r[8];
#pragma unroll
    for (int mf = 0; mf < 4; ++mf) {
        int r = m0 + 16 * mf + (lane >> 2);
        x2r[2 * mf]     = sf[SM_X2 / 4 + r];
        x2r[2 * mf + 1] = sf[SM_X2 / 4 + r + 8];
    }

    // ldmatrix per-lane source row/col within the m16k8 fragment
    const uint32_t rl = lane & 15;
    const uint32_t cl = (lane & 16) >> 2;   // 0 or 4 (floats)

    float* og = out + (size_t)bz * 2048 * 2048;

#pragma unroll 1
    for (int t = 0; t < 4; ++t) {
        const uint32_t ybuf = (t & 1) ? SM_Y1 : SM_Y0;
        const float* yb = sf + ybuf / 4;

        if (t < 3) cp_wait<1>(); else cp_wait<0>();   // y[t] ready
        __syncthreads();

        if (tid < 128) sf[SM_Y2 / 4 + tid] = rowsum128(yb + tid * LDK);
        __syncthreads();

        // ---- MMA mainloop: D(128x128) += X(128x128) * Y^T ----
        float c[4][4][4];
#pragma unroll
        for (int mf = 0; mf < 4; ++mf)
#pragma unroll
            for (int nf = 0; nf < 4; ++nf)
#pragma unroll
                for (int e = 0; e < 4; ++e) c[mf][nf][e] = 0.f;

#pragma unroll
        for (int kk = 0; kk < 16; ++kk) {
            uint32_t a[4][4];
#pragma unroll
            for (int mf = 0; mf < 4; ++mf) {
                uint32_t addr = sb + SM_X +
                    ((uint32_t)((m0 + 16 * mf + rl) * LDK) + (uint32_t)(kk * 8) + cl) * 4u;
                asm volatile(
                    "ldmatrix.sync.aligned.m8n8.x4.shared.b16 {%0,%1,%2,%3}, [%4];"
                    : "=r"(a[mf][0]), "=r"(a[mf][1]), "=r"(a[mf][2]), "=r"(a[mf][3])
                    : "r"(addr));
            }
#pragma unroll
            for (int nf = 0; nf < 4; ++nf) {
                int n = n0w + 8 * nf + (lane >> 2);
                int k = kk * 8 + (lane & 3);
                uint32_t b0 = __float_as_uint(yb[n * LDK + k]);
                uint32_t b1 = __float_as_uint(yb[n * LDK + k + 4]);
#pragma unroll
                for (int mf = 0; mf < 4; ++mf) {
                    asm volatile(
                        "mma.sync.aligned.m16n8k8.row.col.f32.tf32.tf32.f32 "
                        "{%0,%1,%2,%3},{%4,%5,%6,%7},{%8,%9},{%0,%1,%2,%3};"
                        : "+f"(c[mf][nf][0]), "+f"(c[mf][nf][1]),
                          "+f"(c[mf][nf][2]), "+f"(c[mf][nf][3])
                        : "r"(a[mf][0]), "r"(a[mf][1]), "r"(a[mf][2]), "r"(a[mf][3]),
                          "r"(b0), "r"(b1));
                }
            }
        }

        // prefetch y[t+2] into the buffer we just finished reading
        if (t < 2) {
            __syncthreads();   // all warps done reading ybuf
            load_tile_async(sb + ybuf, yg + (size_t)(t + 2) * 128 * 128, tid);
            cp_commit();
        }

        // ---- fused epilogue: max(x2 + y2 - 2*d, 0), coalesced v2 stores ----
        const int ncolbase = bxn * 512 + t * 128 + n0w;
#pragma unroll
        for (int mf = 0; mf < 4; ++mf) {
#pragma unroll
            for (int e2 = 0; e2 < 2; ++e2) {
                int rowg = bym * 128 + m0 + 16 * mf + (lane >> 2) + e2 * 8;
                float xn = x2r[2 * mf + e2];
                float* orow = og + (size_t)rowg * 2048;
#pragma unroll
                for (int nf = 0; nf < 4; ++nf) {
                    int cloc = n0w + 8 * nf + 2 * (lane & 3);
                    float2 yn = *(const float2*)&sf[SM_Y2 / 4 + cloc];
                    float2 o;
                    o.x = fmaxf(fmaf(-2.f, c[mf][nf][e2 * 2 + 0], xn + yn.x), 0.f);
                    o.y = fmaxf(fmaf(-2.f, c[mf][nf][e2 * 2 + 1], xn + yn.y), 0.f);
                    *(float2*)&orow[ncolbase + 8 * nf + 2 * (lane & 3)] = o;
                }
            }
        }
    }
}

extern "C" void kernel_launch(void* const* d_in, const int* in_sizes, int n_in,
                              void* d_out, int out_size) {
    const float* x = (const float*)d_in[0];
    const float* y = (const float*)d_in[1];
    float* out = (float*)d_out;
    cudaFuncSetAttribute(pairwise_cost_kernel,
                         cudaFuncAttributeMaxDynamicSharedMemorySize, SMEM_TOTAL);
    dim3 grid(4, 16, 16);
    pairwise_cost_kernel<<<grid, 256, SMEM_TOTAL>>>(x, y, out);
}